// round 12
// baseline (speedup 1.0000x reference)
#include <cuda_runtime.h>
#include <cuda_bf16.h>
#include <cstdint>

#define TT 4
#define BB 16
#define NTOK 1024
#define CC 512
#define BNC (BB*NTOK*CC)        /* 8388608  */
#define TBNC (TT*BNC)           /* 33554432 */

#define DF1 (1.0f/254.0f)
#define DF2 (1.0f/64516.0f)

// ---------------- scratch ----------------
__device__ int8_t        g_xs[TBNC];
__device__ int8_t        g_k[TBNC];
__device__ int8_t        g_v[TBNC];
__device__ int8_t        g_att[TBNC];
__device__ float         g_Y[TBNC];
__device__ int8_t        g_wq[4][3][CC*CC];   // [widx][digit][n*512+k]
__device__ float         g_wsc[4][CC];        // s0 per column
__device__ int           g_kvcnt[TT*BB*8*64];
__device__ unsigned char g_kvspk[TT*BB*8*64];

// ---------------- PTX helpers (sm_80-class only) ----------------
__device__ __forceinline__ uint32_t smem_u32(const void* p) {
    uint32_t a;
    asm("{ .reg .u64 t; cvta.to.shared.u64 t, %1; cvt.u32.u64 %0, t; }" : "=r"(a) : "l"(p));
    return a;
}
__device__ __forceinline__ void cp_async16(uint32_t dst, const void* src) {
    asm volatile("cp.async.cg.shared.global [%0], [%1], 16;" :: "r"(dst), "l"(src));
}
#define CP_COMMIT() asm volatile("cp.async.commit_group;" ::: "memory")
#define CP_WAIT(n)  asm volatile("cp.async.wait_group %0;" ::"n"(n) : "memory")

__device__ __forceinline__ void ldsm4(uint32_t& r0, uint32_t& r1, uint32_t& r2, uint32_t& r3, uint32_t addr) {
    asm volatile("ldmatrix.sync.aligned.m8n8.x4.shared.b16 {%0,%1,%2,%3}, [%4];"
                 : "=r"(r0), "=r"(r1), "=r"(r2), "=r"(r3) : "r"(addr));
}
__device__ __forceinline__ void mma_s8(int* c, const uint32_t* a, const uint32_t* b) {
    asm volatile("mma.sync.aligned.m16n8k32.row.col.s32.s8.s8.s32 "
                 "{%0,%1,%2,%3}, {%4,%5,%6,%7}, {%8,%9}, {%0,%1,%2,%3};"
                 : "+r"(c[0]), "+r"(c[1]), "+r"(c[2]), "+r"(c[3])
                 : "r"(a[0]), "r"(a[1]), "r"(a[2]), "r"(a[3]), "r"(b[0]), "r"(b[1]));
}

// ---------------- weight quantization: per-column 3x int8 digits, transposed to [n][k] ----------------
__global__ void wquant_kernel(const float* __restrict__ W, int widx)
{
    __shared__ float red[256];
    __shared__ float s0sh;
    const int n = blockIdx.x;          // output column
    const int tid = threadIdx.x;       // 256
    float w0 = W[(size_t)tid*512 + n];
    float w1 = W[(size_t)(tid + 256)*512 + n];
    float m = fmaxf(fabsf(w0), fabsf(w1));
    red[tid] = m;
    __syncthreads();
    for (int s = 128; s > 0; s >>= 1) {
        if (tid < s) red[tid] = fmaxf(red[tid], red[tid + s]);
        __syncthreads();
    }
    if (tid == 0) {
        float s0 = fmaxf(red[0], 1e-30f) / 127.0f;
        s0sh = s0;
        g_wsc[widx][n] = s0;
    }
    __syncthreads();
    const float s0 = s0sh, s1 = s0*DF1, s2 = s0*DF2;
    #pragma unroll
    for (int half = 0; half < 2; half++) {
        float w = half ? w1 : w0;
        int k = tid + half*256;
        float i0 = rintf(w / s0);
        float r1 = w - s0*i0;
        float i1 = rintf(r1 / s1);
        float r2 = r1 - s1*i1;
        float i2 = rintf(r2 / s2);
        size_t o = (size_t)n*512 + k;
        g_wq[widx][0][o] = (int8_t)(int)i0;
        g_wq[widx][1][o] = (int8_t)(int)i1;
        g_wq[widx][2][o] = (int8_t)(int)i2;
    }
}

// ---------------- IMMA GEMM: Y[M,512] = A(s8 {0,1})[M,512] @ sum_d s_d * Wd^T ----------------
// CTA 128x128, 16 warps (4x4), warp tile 32x32. K: 4 chunks of 128 s8, x3 digits = 12 stages.
#define GSMEM_BYTES (65536 + 1024)

__device__ __forceinline__ void load_tile_128(uint32_t buf, const int8_t* src, int kc, int tid)
{
    // 128 rows x 128 s8 (128B/row), SW128-xor swizzle; src row stride 512B
    const char* s0 = (const char*)src + kc*128;
    #pragma unroll
    for (int it = 0; it < 2; it++) {
        int idx = it*512 + tid;              // 0..1023
        int r = idx >> 3, c16 = idx & 7;
        uint32_t off = (uint32_t)r*128 + c16*16;
        cp_async16(buf + (off ^ ((off >> 3) & 0x70)), s0 + (size_t)r*512 + c16*16);
    }
}

__global__ __launch_bounds__(512, 1) void gemm_i8_kernel(int widx, int use_att)
{
    extern __shared__ char dsm[];
    uint32_t sb = (smem_u32(dsm) + 1023) & ~1023u;
    const uint32_t A_OFF = sb;               // 2 x 16KB
    const uint32_t B_OFF = sb + 32768;       // 2 x 16KB
    const int tid = threadIdx.x, lane = tid & 31, wid = tid >> 5;
    const int wm = wid >> 2, wn = wid & 3;   // warp grid 4(M) x 4(N)
    const int gq = lane >> 2, qt = lane & 3;

    const int by = blockIdx.x >> 2, bx = blockIdx.x & 3;
    const int8_t* Asrc = (use_att ? g_att : g_xs) + (size_t)by*128*512;
    const int8_t* Wd[3];
    #pragma unroll
    for (int d = 0; d < 3; d++) Wd[d] = g_wq[widx][d] + (size_t)bx*128*512;

    // per-thread column scales (8 columns: 4 nb x 2)
    float2 scb[4];
    #pragma unroll
    for (int nb = 0; nb < 4; nb++)
        scb[nb] = *(const float2*)&g_wsc[widx][bx*128 + wn*32 + nb*8 + qt*2];

    int   accI[2][4][4];
    float accF[2][4][4];
    #pragma unroll
    for (int mb = 0; mb < 2; mb++)
        #pragma unroll
        for (int nb = 0; nb < 4; nb++)
            #pragma unroll
            for (int q = 0; q < 4; q++) { accI[mb][nb][q] = 0; accF[mb][nb][q] = 0.f; }

    // stage s: digit d = s>>2, chunk kc = s&3; A & B double buffered by s&1
    load_tile_128(A_OFF, Asrc, 0, tid);
    load_tile_128(B_OFF, Wd[0], 0, tid);
    CP_COMMIT();
    load_tile_128(A_OFF + 16384, Asrc, 1, tid);
    load_tile_128(B_OFF + 16384, Wd[0], 1, tid);
    CP_COMMIT();

    for (int s = 0; s < 12; s++) {
        if (s < 11) CP_WAIT(1); else CP_WAIT(0);
        __syncthreads();

        // compute stage s
        {
            uint32_t abase = A_OFF + (s & 1)*16384;
            uint32_t bbase = B_OFF + (s & 1)*16384;
            #pragma unroll
            for (int ks = 0; ks < 4; ks++) {       // 4 x k32 per 128B chunk
                uint32_t a[2][4];
                #pragma unroll
                for (int mb = 0; mb < 2; mb++) {
                    uint32_t row = wm*32 + mb*16 + (lane & 15);
                    uint32_t kb  = ks*32 + ((lane >> 4) << 4);
                    uint32_t off = row*128 + kb;
                    ldsm4(a[mb][0], a[mb][1], a[mb][2], a[mb][3],
                          abase + (off ^ ((off >> 3) & 0x70)));
                }
                uint32_t b[4][2];
                #pragma unroll
                for (int nb2 = 0; nb2 < 2; nb2++) {
                    uint32_t row = wn*32 + nb2*16 + (lane & 7) + ((lane >> 4) << 3);
                    uint32_t kb  = ks*32 + (((lane >> 3) & 1) << 4);
                    uint32_t off = row*128 + kb;
                    ldsm4(b[nb2*2][0], b[nb2*2][1], b[nb2*2+1][0], b[nb2*2+1][1],
                          bbase + (off ^ ((off >> 3) & 0x70)));
                }
                #pragma unroll
                for (int mb = 0; mb < 2; mb++)
                    #pragma unroll
                    for (int nb = 0; nb < 4; nb++)
                        mma_s8(accI[mb][nb], a[mb], b[nb]);
            }
        }
        __syncthreads();

        // issue stage s+2 loads
        if (s + 2 < 12) {
            int s2 = s + 2;
            int d2 = s2 >> 2, kc2 = s2 & 3;
            load_tile_128(A_OFF + (s2 & 1)*16384, Asrc, kc2, tid);
            load_tile_128(B_OFF + (s2 & 1)*16384, Wd[d2], kc2, tid);
            CP_COMMIT();
        }

        // end of digit: fold s32 -> f32 with per-column scale, reset s32
        if ((s & 3) == 3) {
            int d = s >> 2;
            float df = (d == 0) ? 1.0f : (d == 1) ? DF1 : DF2;
            #pragma unroll
            for (int nb = 0; nb < 4; nb++) {
                float fx = scb[nb].x * df, fy = scb[nb].y * df;
                #pragma unroll
                for (int mb = 0; mb < 2; mb++) {
                    accF[mb][nb][0] += fx * (float)accI[mb][nb][0];
                    accF[mb][nb][1] += fy * (float)accI[mb][nb][1];
                    accF[mb][nb][2] += fx * (float)accI[mb][nb][2];
                    accF[mb][nb][3] += fy * (float)accI[mb][nb][3];
                    accI[mb][nb][0] = 0; accI[mb][nb][1] = 0;
                    accI[mb][nb][2] = 0; accI[mb][nb][3] = 0;
                }
            }
        }
    }

    // epilogue
    #pragma unroll
    for (int mb = 0; mb < 2; mb++) {
        #pragma unroll
        for (int nb = 0; nb < 4; nb++) {
            size_t row0 = (size_t)by*128 + wm*32 + mb*16 + gq;
            size_t col  = (size_t)bx*128 + wn*32 + nb*8 + qt*2;
            *(float2*)(g_Y + row0*512 + col)     = make_float2(accF[mb][nb][0], accF[mb][nb][1]);
            *(float2*)(g_Y + (row0+8)*512 + col) = make_float2(accF[mb][nb][2], accF[mb][nb][3]);
        }
    }
}

// ---------------- LIF over input x -> xs spikes (s8) ----------------
__global__ void lif_x_kernel(const float* __restrict__ x)
{
    int i = blockIdx.x * blockDim.x + threadIdx.x;
    if (i >= BNC/4) return;
    const float4* x4 = (const float4*)x;
    uchar4* xs4 = (uchar4*)g_xs;
    float4 v = make_float4(0.f, 0.f, 0.f, 0.f);
    #pragma unroll
    for (int t = 0; t < TT; t++) {
        float4 xv = x4[t*(BNC/4) + i];
        v.x += (xv.x - v.x)*0.5f; v.y += (xv.y - v.y)*0.5f;
        v.z += (xv.z - v.z)*0.5f; v.w += (xv.w - v.w)*0.5f;
        uchar4 s;
        s.x = (v.x >= 1.0f); s.y = (v.y >= 1.0f); s.z = (v.z >= 1.0f); s.w = (v.w >= 1.0f);
        if (s.x) v.x = 0.f; if (s.y) v.y = 0.f; if (s.z) v.z = 0.f; if (s.w) v.w = 0.f;
        xs4[t*(BNC/4) + i] = s;
    }
}

// ---------------- bn + LIF over Y -> s8 spikes; sel: 0=q(+att mask), 1=k, 2=v(+vout) ----------------
__global__ void lif_bn_kernel(const float* __restrict__ bias,
                              const float* __restrict__ bnp,
                              int sel, float* __restrict__ vout)
{
    int i = blockIdx.x * blockDim.x + threadIdx.x;
    if (i >= BNC/4) return;
    const int c = (i & 127)*4;
    float4 ga = *(const float4*)(bnp + c);
    float4 be = *(const float4*)(bnp + 512 + c);
    float4 mu = *(const float4*)(bnp + 1024 + c);
    float4 va = *(const float4*)(bnp + 1536 + c);
    float4 rs;
    rs.x = rsqrtf(va.x + 1e-5f); rs.y = rsqrtf(va.y + 1e-5f);
    rs.z = rsqrtf(va.z + 1e-5f); rs.w = rsqrtf(va.w + 1e-5f);
    float4 bb = make_float4(0.f, 0.f, 0.f, 0.f);
    if (bias) bb = *(const float4*)(bias + c);

    uchar4* dst = (sel == 0) ? (uchar4*)g_att : (sel == 1) ? (uchar4*)g_k : (uchar4*)g_v;
    const float4* Y4 = (const float4*)g_Y;

    const int b = i >> 17;
    const int r = i & 131071;
    const int n = r >> 7;
    const int h = c >> 6;
    const int d = c & 63;

    float4 v = make_float4(0.f, 0.f, 0.f, 0.f);
    #pragma unroll
    for (int t = 0; t < TT; t++) {
        float4 y = Y4[t*(BNC/4) + i];
        float ux = ga.x*((y.x + bb.x) - mu.x)*rs.x + be.x;
        float uy = ga.y*((y.y + bb.y) - mu.y)*rs.y + be.y;
        float uz = ga.z*((y.z + bb.z) - mu.z)*rs.z + be.z;
        float uw = ga.w*((y.w + bb.w) - mu.w)*rs.w + be.w;
        v.x += (ux - v.x)*0.5f; v.y += (uy - v.y)*0.5f;
        v.z += (uz - v.z)*0.5f; v.w += (uw - v.w)*0.5f;
        uchar4 s;
        s.x = (v.x >= 1.0f); s.y = (v.y >= 1.0f); s.z = (v.z >= 1.0f); s.w = (v.w >= 1.0f);
        if (s.x) v.x = 0.f; if (s.y) v.y = 0.f; if (s.z) v.z = 0.f; if (s.w) v.w = 0.f;
        if (sel == 0) {   // q: apply talking-heads kv mask -> att directly
            uchar4 mm = *(const uchar4*)(g_kvspk + ((t*BB + b)*8 + h)*64 + d);
            s.x &= mm.x; s.y &= mm.y; s.z &= mm.z; s.w &= mm.w;
        }
        dst[t*(BNC/4) + i] = s;
        if (sel == 2 && vout) {
            float4 fs = make_float4((float)s.x, (float)s.y, (float)s.z, (float)s.w);
            *(float4*)(vout + ((((size_t)(t*BB + b)*8 + h)*1024 + n)*64 + d)) = fs;
        }
    }
}

// ---------------- kv = sum_n k*v (integer-exact) ----------------
__global__ void kv_count_kernel()
{
    const int bid = blockIdx.x;          // (t*16+b)*8+h
    const int tid = threadIdx.x;         // 256
    const int d4 = tid & 15, g = tid >> 4;
    const int h = bid & 7;
    const int tb = bid >> 3;
    const size_t base = (size_t)tb*1024*512 + h*64 + d4*4;
    int a0=0, a1=0, a2=0, a3=0;
    for (int nn = 0; nn < 64; nn++) {
        size_t off = base + (size_t)(g*64 + nn)*512;
        uchar4 kk = *(const uchar4*)(g_k + off);
        uchar4 vv = *(const uchar4*)(g_v + off);
        a0 += kk.x & vv.x; a1 += kk.y & vv.y; a2 += kk.z & vv.z; a3 += kk.w & vv.w;
    }
    __shared__ int4 s[16][16];
    s[g][d4] = make_int4(a0, a1, a2, a3);
    __syncthreads();
    if (tid < 16) {
        int4 tot = make_int4(0, 0, 0, 0);
        #pragma unroll
        for (int gg = 0; gg < 16; gg++) {
            tot.x += s[gg][tid].x; tot.y += s[gg][tid].y;
            tot.z += s[gg][tid].z; tot.w += s[gg][tid].w;
        }
        ((int4*)g_kvcnt)[bid*16 + tid] = tot;
    }
}

__global__ void lif_kv_kernel()
{
    int i = blockIdx.x * blockDim.x + threadIdx.x;   // BB*8*64 = 8192
    if (i >= BB*8*64) return;
    float m = 0.f;
    #pragma unroll
    for (int t = 0; t < TT; t++) {
        float cnt = (float)g_kvcnt[t*8192 + i];
        m += (cnt - m)*0.5f;
        unsigned char sm = (m >= 0.5f) ? 1u : 0u;
        g_kvspk[t*8192 + i] = sm;
        if (sm) m = 0.f;
    }
}

// ---------------- final bn + identity ----------------
__global__ void out_kernel(const float* __restrict__ x,
                           const float* __restrict__ bp,
                           const float* __restrict__ bnp,
                           float* __restrict__ out)
{
    int i = blockIdx.x * blockDim.x + threadIdx.x;   // TBNC/4
    if (i >= TBNC/4) return;
    const int c = (i & 127)*4;
    float4 ga = *(const float4*)(bnp + c);
    float4 be = *(const float4*)(bnp + 512 + c);
    float4 mu = *(const float4*)(bnp + 1024 + c);
    float4 va = *(const float4*)(bnp + 1536 + c);
    float4 b  = *(const float4*)(bp + c);
    float4 y  = ((const float4*)g_Y)[i];
    float4 xv = ((const float4*)x)[i];
    float4 o;
    o.x = ga.x*((y.x + b.x) - mu.x)*rsqrtf(va.x + 1e-5f) + be.x + xv.x;
    o.y = ga.y*((y.y + b.y) - mu.y)*rsqrtf(va.y + 1e-5f) + be.y + xv.y;
    o.z = ga.z*((y.z + b.z) - mu.z)*rsqrtf(va.z + 1e-5f) + be.z + xv.z;
    o.w = ga.w*((y.w + b.w) - mu.w)*rsqrtf(va.w + 1e-5f) + be.w + xv.w;
    ((float4*)out)[i] = o;
}

// ---------------- launch ----------------
extern "C" void kernel_launch(void* const* d_in, const int* in_sizes, int n_in,
                              void* d_out, int out_size)
{
    const float* x    = (const float*)d_in[0];
    const float* Wq   = (const float*)d_in[1];
    const float* bq   = (const float*)d_in[2];
    const float* Wk   = (const float*)d_in[3];
    const float* bk   = (const float*)d_in[4];
    const float* Wv   = (const float*)d_in[5];
    const float* Wp   = (const float*)d_in[6];
    const float* bp   = (const float*)d_in[7];
    const float* bn_q = (const float*)d_in[8];
    const float* bn_k = (const float*)d_in[9];
    const float* bn_v = (const float*)d_in[10];
    const float* bn_p = (const float*)d_in[11];
    float* out  = (float*)d_out;
    float* vout = (out_size >= 2*TBNC) ? (out + TBNC) : nullptr;

    cudaFuncSetAttribute(gemm_i8_kernel, cudaFuncAttributeMaxDynamicSharedMemorySize, GSMEM_BYTES);

    lif_x_kernel<<<(BNC/4 + 255)/256, 256>>>(x);
    wquant_kernel<<<512, 256>>>(Wq, 0);
    wquant_kernel<<<512, 256>>>(Wk, 1);
    wquant_kernel<<<512, 256>>>(Wv, 2);
    wquant_kernel<<<512, 256>>>(Wp, 3);

    const int GG = 512*4;   // (65536/128) x (512/128)

    // K, then V, then kv, then Q (att fused), then P
    gemm_i8_kernel<<<GG, 512, GSMEM_BYTES>>>(1, 0);
    lif_bn_kernel<<<(BNC/4 + 255)/256, 256>>>(bk, bn_k, 1, nullptr);

    gemm_i8_kernel<<<GG, 512, GSMEM_BYTES>>>(2, 0);
    lif_bn_kernel<<<(BNC/4 + 255)/256, 256>>>(nullptr, bn_v, 2, vout);

    kv_count_kernel<<<TT*BB*8, 256>>>();
    lif_kv_kernel<<<(BB*8*64 + 255)/256, 256>>>();

    gemm_i8_kernel<<<GG, 512, GSMEM_BYTES>>>(0, 0);
    lif_bn_kernel<<<(BNC/4 + 255)/256, 256>>>(bq, bn_q, 0, nullptr);

    gemm_i8_kernel<<<GG, 512, GSMEM_BYTES>>>(3, 1);
    out_kernel<<<(TBNC/4 + 255)/256, 256>>>(x, bp, bn_p, out);
}

// round 15
// speedup vs baseline: 2.5892x; 2.5892x over previous
#include <cuda_runtime.h>
#include <cuda_bf16.h>
#include <cstdint>

#define TT 4
#define BB 16
#define NTOK 1024
#define CC 512
#define BNC (BB*NTOK*CC)        /* 8388608  */
#define TBNC (TT*BNC)           /* 33554432 */

// ---------------- scratch ----------------
__device__ __nv_bfloat16 g_xs_bf[TBNC];
__device__ __nv_bfloat16 g_k_bf[TBNC];
__device__ __nv_bfloat16 g_v_bf[TBNC];
__device__ __nv_bfloat16 g_att_bf[TBNC];
__device__ float         g_Y[TBNC];
__device__ __nv_bfloat16 g_wt[4][3][CC*CC];
__device__ int           g_kvcnt[TT*BB*8*64];
__device__ unsigned short g_kvspk[TT*BB*8*64];

// ---------------- PTX helpers (sm_80-compatible only) ----------------
__device__ __forceinline__ uint32_t smem_u32(const void* p) {
    uint32_t a;
    asm("{ .reg .u64 t; cvta.to.shared.u64 t, %1; cvt.u32.u64 %0, t; }" : "=r"(a) : "l"(p));
    return a;
}
__device__ __forceinline__ void cp_async16(uint32_t dst, const void* src) {
    asm volatile("cp.async.cg.shared.global [%0], [%1], 16;" :: "r"(dst), "l"(src));
}
#define CP_COMMIT() asm volatile("cp.async.commit_group;" ::: "memory")
#define CP_WAIT(n)  asm volatile("cp.async.wait_group %0;" ::"n"(n) : "memory")

__device__ __forceinline__ void ldsm4(uint32_t& r0, uint32_t& r1, uint32_t& r2, uint32_t& r3, uint32_t addr) {
    asm volatile("ldmatrix.sync.aligned.m8n8.x4.shared.b16 {%0,%1,%2,%3}, [%4];"
                 : "=r"(r0), "=r"(r1), "=r"(r2), "=r"(r3) : "r"(addr));
}
__device__ __forceinline__ void mma_bf16(float* c, const uint32_t* a, const uint32_t* b) {
    asm volatile("mma.sync.aligned.m16n8k16.row.col.f32.bf16.bf16.f32 "
                 "{%0,%1,%2,%3}, {%4,%5,%6,%7}, {%8,%9}, {%0,%1,%2,%3};"
                 : "+f"(c[0]), "+f"(c[1]), "+f"(c[2]), "+f"(c[3])
                 : "r"(a[0]), "r"(a[1]), "r"(a[2]), "r"(a[3]), "r"(b[0]), "r"(b[1]));
}

// ---------------- weight split + transpose: g_wt[w][s][n*512+k] ----------------
__global__ void wsplit_kernel(const float* __restrict__ W, int widx)
{
    __shared__ float t[32][33];
    int bx = blockIdx.x & 15, by = blockIdx.x >> 4;
    int x = threadIdx.x & 31, y = threadIdx.x >> 5;   // y: 0..7
    #pragma unroll
    for (int i = 0; i < 4; i++)
        t[y + 8*i][x] = W[(by*32 + y + 8*i)*512 + bx*32 + x];
    __syncthreads();
    #pragma unroll
    for (int i = 0; i < 4; i++) {
        float w = t[x][y + 8*i];
        int n = bx*32 + y + 8*i, k = by*32 + x;
        __nv_bfloat16 h0 = __float2bfloat16(w);
        float r1 = w - __bfloat162float(h0);
        __nv_bfloat16 h1 = __float2bfloat16(r1);
        float r2 = r1 - __bfloat162float(h1);
        __nv_bfloat16 h2 = __float2bfloat16(r2);
        size_t o = (size_t)n*512 + k;
        g_wt[widx][0][o] = h0; g_wt[widx][1][o] = h1; g_wt[widx][2][o] = h2;
    }
}

// ---------------- HMMA GEMM: Y[M,512] = A(bf16 {0,1})[M,512] @ (w0+w1+w2)^T ----------------
// CTA 256x128, 8 warps (4M x 2N), warp tile 64x64.
// Stage s (0..23): kc = s/3 (K chunk of 64), split = s%3.
// A: 256x64 bf16 = 32KB, double-buffered by (kc&1), loaded only on split==0.
// B: 128x64 bf16 = 16KB, triple-buffered by (s%3).
// One cp.async commit group per stage; depth-2 prefetch; ONE __syncthreads per stage.
#define GSMEM_BYTES (65536 + 49152 + 1024)

__device__ __forceinline__ void load_A_256(uint32_t buf, const __nv_bfloat16* src, int kc, int tid)
{
    // 256 rows x 64 bf16 (128B/row), SW128-xor swizzle; src row stride 1024B
    const char* s0 = (const char*)src + kc*128;
    #pragma unroll
    for (int it = 0; it < 8; it++) {
        int idx = it*256 + tid;              // 0..2047
        int r = idx >> 3, c16 = idx & 7;
        uint32_t off = (uint32_t)r*128 + c16*16;
        cp_async16(buf + (off ^ ((off >> 3) & 0x70)), s0 + (size_t)r*1024 + c16*16);
    }
}
__device__ __forceinline__ void load_B_128(uint32_t buf, const __nv_bfloat16* src, int kc, int tid)
{
    const char* s0 = (const char*)src + kc*128;
    #pragma unroll
    for (int it = 0; it < 4; it++) {
        int idx = it*256 + tid;              // 0..1023
        int r = idx >> 3, c16 = idx & 7;
        uint32_t off = (uint32_t)r*128 + c16*16;
        cp_async16(buf + (off ^ ((off >> 3) & 0x70)), s0 + (size_t)r*1024 + c16*16);
    }
}

__global__ __launch_bounds__(256, 1) void gemm_mma_kernel(int widx, int use_att)
{
    extern __shared__ char dsm[];
    uint32_t sb = (smem_u32(dsm) + 1023) & ~1023u;
    const uint32_t A_OFF = sb;               // 2 x 32KB
    const uint32_t B_OFF = sb + 65536;       // 3 x 16KB
    const int tid = threadIdx.x, lane = tid & 31, wid = tid >> 5;
    const int wm = wid >> 1, wn = wid & 1;   // warp grid 4(M) x 2(N)

    const int by = blockIdx.x >> 2, bx = blockIdx.x & 3;
    const __nv_bfloat16* Asrc = (use_att ? g_att_bf : g_xs_bf) + (size_t)by*256*512;
    const __nv_bfloat16* Ws[3];
    #pragma unroll
    for (int d = 0; d < 3; d++) Ws[d] = g_wt[widx][d] + (size_t)bx*128*512;

    float acc[4][8][4];
    #pragma unroll
    for (int i = 0; i < 4; i++)
        #pragma unroll
        for (int j = 0; j < 8; j++)
            #pragma unroll
            for (int q = 0; q < 4; q++) acc[i][j][q] = 0.f;

    // prologue: stage 0 (A kc0 + B split0), stage 1 (B split1)
    load_A_256(A_OFF, Asrc, 0, tid);
    load_B_128(B_OFF, Ws[0], 0, tid);
    CP_COMMIT();
    load_B_128(B_OFF + 16384, Ws[1], 0, tid);
    CP_COMMIT();

    int kc = 0, split = 0;
    for (int s = 0; s < 24; s++) {
        if (s < 23) CP_WAIT(1); else CP_WAIT(0);
        __syncthreads();

        // issue stage s+2 loads (into buffers last touched at stage s-1 -> safe after this sync)
        if (s + 2 < 24) {
            int s2 = s + 2;
            int kc2 = s2 / 3, sp2 = s2 - kc2*3;
            if (sp2 == 0) load_A_256(A_OFF + (kc2 & 1)*32768, Asrc, kc2, tid);
            load_B_128(B_OFF + (s2 % 3)*16384, Ws[sp2], kc2, tid);
        }
        CP_COMMIT();   // one group per stage (possibly empty)

        // compute stage s
        {
            uint32_t abase = A_OFF + (kc & 1)*32768;
            uint32_t bbase = B_OFF + (s % 3)*16384;
            #pragma unroll
            for (int ks = 0; ks < 4; ks++) {       // 4 x k16
                uint32_t a[4][4];
                #pragma unroll
                for (int mb = 0; mb < 4; mb++) {
                    uint32_t row = wm*64 + mb*16 + (lane & 15);
                    uint32_t kb  = ks*32 + ((lane >> 4) << 4);
                    uint32_t off = row*128 + kb;
                    ldsm4(a[mb][0], a[mb][1], a[mb][2], a[mb][3],
                          abase + (off ^ ((off >> 3) & 0x70)));
                }
                uint32_t b[8][2];
                #pragma unroll
                for (int nb2 = 0; nb2 < 4; nb2++) {
                    uint32_t row = wn*64 + nb2*16 + (lane & 7) + ((lane >> 4) << 3);
                    uint32_t kb  = ks*32 + (((lane >> 3) & 1) << 4);
                    uint32_t off = row*128 + kb;
                    ldsm4(b[nb2*2][0], b[nb2*2][1], b[nb2*2+1][0], b[nb2*2+1][1],
                          bbase + (off ^ ((off >> 3) & 0x70)));
                }
                #pragma unroll
                for (int mb = 0; mb < 4; mb++)
                    #pragma unroll
                    for (int nb = 0; nb < 8; nb++)
                        mma_bf16(acc[mb][nb], a[mb], b[nb]);
            }
        }

        split++; if (split == 3) { split = 0; kc++; }
    }

    // epilogue
    const int gq = lane >> 2, qt = lane & 3;
    #pragma unroll
    for (int mb = 0; mb < 4; mb++) {
        #pragma unroll
        for (int nb = 0; nb < 8; nb++) {
            size_t row0 = (size_t)by*256 + wm*64 + mb*16 + gq;
            size_t col  = (size_t)bx*128 + wn*64 + nb*8 + qt*2;
            *(float2*)(g_Y + row0*512 + col)     = make_float2(acc[mb][nb][0], acc[mb][nb][1]);
            *(float2*)(g_Y + (row0+8)*512 + col) = make_float2(acc[mb][nb][2], acc[mb][nb][3]);
        }
    }
}

// ---------------- LIF over input x -> xs spikes (bf16) ----------------
__global__ void lif_x_kernel(const float* __restrict__ x)
{
    int i = blockIdx.x * blockDim.x + threadIdx.x;
    if (i >= BNC/4) return;
    const float4* x4 = (const float4*)x;
    uint2* xs2 = (uint2*)g_xs_bf;
    float4 v = make_float4(0.f, 0.f, 0.f, 0.f);
    #pragma unroll
    for (int t = 0; t < TT; t++) {
        float4 xv = x4[t*(BNC/4) + i];
        v.x += (xv.x - v.x)*0.5f; v.y += (xv.y - v.y)*0.5f;
        v.z += (xv.z - v.z)*0.5f; v.w += (xv.w - v.w)*0.5f;
        unsigned s0 = (v.x >= 1.0f), s1 = (v.y >= 1.0f), s2 = (v.z >= 1.0f), s3 = (v.w >= 1.0f);
        if (s0) v.x = 0.f; if (s1) v.y = 0.f; if (s2) v.z = 0.f; if (s3) v.w = 0.f;
        uint2 o;
        o.x = (s0 ? 0x3F80u : 0u) | ((s1 ? 0x3F80u : 0u) << 16);
        o.y = (s2 ? 0x3F80u : 0u) | ((s3 ? 0x3F80u : 0u) << 16);
        xs2[t*(BNC/4) + i] = o;
    }
}

// ---------------- bn + LIF over Y -> bf16 spikes; sel: 0=q(+att mask), 1=k, 2=v(+vout) ----------------
__global__ void lif_bn_kernel(const float* __restrict__ bias,
                              const float* __restrict__ bnp,
                              int sel, float* __restrict__ vout)
{
    int i = blockIdx.x * blockDim.x + threadIdx.x;
    if (i >= BNC/4) return;
    const int c = (i & 127)*4;
    float4 ga = *(const float4*)(bnp + c);
    float4 be = *(const float4*)(bnp + 512 + c);
    float4 mu = *(const float4*)(bnp + 1024 + c);
    float4 va = *(const float4*)(bnp + 1536 + c);
    float4 rs;
    rs.x = rsqrtf(va.x + 1e-5f); rs.y = rsqrtf(va.y + 1e-5f);
    rs.z = rsqrtf(va.z + 1e-5f); rs.w = rsqrtf(va.w + 1e-5f);
    float4 bb = make_float4(0.f, 0.f, 0.f, 0.f);
    if (bias) bb = *(const float4*)(bias + c);

    uint2* dst = (sel == 0) ? (uint2*)g_att_bf : (sel == 1) ? (uint2*)g_k_bf : (uint2*)g_v_bf;
    const float4* Y4 = (const float4*)g_Y;

    const int b = i >> 17;
    const int r = i & 131071;
    const int n = r >> 7;
    const int h = c >> 6;
    const int d = c & 63;

    float4 v = make_float4(0.f, 0.f, 0.f, 0.f);
    #pragma unroll
    for (int t = 0; t < TT; t++) {
        float4 y = Y4[t*(BNC/4) + i];
        float ux = ga.x*((y.x + bb.x) - mu.x)*rs.x + be.x;
        float uy = ga.y*((y.y + bb.y) - mu.y)*rs.y + be.y;
        float uz = ga.z*((y.z + bb.z) - mu.z)*rs.z + be.z;
        float uw = ga.w*((y.w + bb.w) - mu.w)*rs.w + be.w;
        v.x += (ux - v.x)*0.5f; v.y += (uy - v.y)*0.5f;
        v.z += (uz - v.z)*0.5f; v.w += (uw - v.w)*0.5f;
        unsigned s0 = (v.x >= 1.0f), s1 = (v.y >= 1.0f), s2 = (v.z >= 1.0f), s3 = (v.w >= 1.0f);
        if (s0) v.x = 0.f; if (s1) v.y = 0.f; if (s2) v.z = 0.f; if (s3) v.w = 0.f;
        uint2 o;
        o.x = (s0 ? 0x3F80u : 0u) | ((s1 ? 0x3F80u : 0u) << 16);
        o.y = (s2 ? 0x3F80u : 0u) | ((s3 ? 0x3F80u : 0u) << 16);
        if (sel == 0) {   // q: apply talking-heads kv mask -> att directly
            uint2 mm = *(const uint2*)(g_kvspk + ((t*BB + b)*8 + h)*64 + d);
            o.x &= mm.x; o.y &= mm.y;
        }
        dst[t*(BNC/4) + i] = o;
        if (sel == 2 && vout) {
            float4 fs = make_float4((float)s0, (float)s1, (float)s2, (float)s3);
            *(float4*)(vout + ((((size_t)(t*BB + b)*8 + h)*1024 + n)*64 + d)) = fs;
        }
    }
}

// ---------------- kv = sum_n k*v (integer-exact, bf16 inputs) ----------------
__global__ void kv_count_kernel()
{
    const int bid = blockIdx.x;          // (t*16+b)*8+h
    const int tid = threadIdx.x;         // 256
    const int d4 = tid & 15, g = tid >> 4;
    const int h = bid & 7;
    const int tb = bid >> 3;
    const size_t base = (size_t)tb*1024*512 + h*64 + d4*4;
    int a0=0, a1=0, a2=0, a3=0;
    for (int nn = 0; nn < 64; nn++) {
        size_t off = base + (size_t)(g*64 + nn)*512;
        uint2 kk = *(const uint2*)(g_k_bf + off);
        uint2 vv = *(const uint2*)(g_v_bf + off);
        unsigned m0 = kk.x & vv.x, m1 = kk.y & vv.y;
        a0 += (m0 & 0xFFFFu) ? 1 : 0; a1 += (m0 >> 16) ? 1 : 0;
        a2 += (m1 & 0xFFFFu) ? 1 : 0; a3 += (m1 >> 16) ? 1 : 0;
    }
    __shared__ int4 s[16][16];
    s[g][d4] = make_int4(a0, a1, a2, a3);
    __syncthreads();
    if (tid < 16) {
        int4 tot = make_int4(0, 0, 0, 0);
        #pragma unroll
        for (int gg = 0; gg < 16; gg++) {
            tot.x += s[gg][tid].x; tot.y += s[gg][tid].y;
            tot.z += s[gg][tid].z; tot.w += s[gg][tid].w;
        }
        ((int4*)g_kvcnt)[bid*16 + tid] = tot;
    }
}

__global__ void lif_kv_kernel()
{
    int i = blockIdx.x * blockDim.x + threadIdx.x;   // BB*8*64 = 8192
    if (i >= BB*8*64) return;
    float m = 0.f;
    #pragma unroll
    for (int t = 0; t < TT; t++) {
        float cnt = (float)g_kvcnt[t*8192 + i];
        m += (cnt - m)*0.5f;
        unsigned short sm = (m >= 0.5f) ? 0xFFFFu : 0u;
        g_kvspk[t*8192 + i] = sm;
        if (sm) m = 0.f;
    }
}

// ---------------- final bn + identity ----------------
__global__ void out_kernel(const float* __restrict__ x,
                           const float* __restrict__ bp,
                           const float* __restrict__ bnp,
                           float* __restrict__ out)
{
    int i = blockIdx.x * blockDim.x + threadIdx.x;   // TBNC/4
    if (i >= TBNC/4) return;
    const int c = (i & 127)*4;
    float4 ga = *(const float4*)(bnp + c);
    float4 be = *(const float4*)(bnp + 512 + c);
    float4 mu = *(const float4*)(bnp + 1024 + c);
    float4 va = *(const float4*)(bnp + 1536 + c);
    float4 b  = *(const float4*)(bp + c);
    float4 y  = ((const float4*)g_Y)[i];
    float4 xv = ((const float4*)x)[i];
    float4 o;
    o.x = ga.x*((y.x + b.x) - mu.x)*rsqrtf(va.x + 1e-5f) + be.x + xv.x;
    o.y = ga.y*((y.y + b.y) - mu.y)*rsqrtf(va.y + 1e-5f) + be.y + xv.y;
    o.z = ga.z*((y.z + b.z) - mu.z)*rsqrtf(va.z + 1e-5f) + be.z + xv.z;
    o.w = ga.w*((y.w + b.w) - mu.w)*rsqrtf(va.w + 1e-5f) + be.w + xv.w;
    ((float4*)out)[i] = o;
}

// ---------------- launch ----------------
extern "C" void kernel_launch(void* const* d_in, const int* in_sizes, int n_in,
                              void* d_out, int out_size)
{
    const float* x    = (const float*)d_in[0];
    const float* Wq   = (const float*)d_in[1];
    const float* bq   = (const float*)d_in[2];
    const float* Wk   = (const float*)d_in[3];
    const float* bk   = (const float*)d_in[4];
    const float* Wv   = (const float*)d_in[5];
    const float* Wp   = (const float*)d_in[6];
    const float* bp   = (const float*)d_in[7];
    const float* bn_q = (const float*)d_in[8];
    const float* bn_k = (const float*)d_in[9];
    const float* bn_v = (const float*)d_in[10];
    const float* bn_p = (const float*)d_in[11];
    float* out  = (float*)d_out;
    float* vout = (out_size >= 2*TBNC) ? (out + TBNC) : nullptr;

    cudaFuncSetAttribute(gemm_mma_kernel, cudaFuncAttributeMaxDynamicSharedMemorySize, GSMEM_BYTES);

    lif_x_kernel<<<(BNC/4 + 255)/256, 256>>>(x);
    wsplit_kernel<<<256, 256>>>(Wq, 0);
    wsplit_kernel<<<256, 256>>>(Wk, 1);
    wsplit_kernel<<<256, 256>>>(Wv, 2);
    wsplit_kernel<<<256, 256>>>(Wp, 3);

    const int GG = 256*4;   // (65536/256) x (512/128)

    // K, then V, then kv, then Q (att fused), then P
    gemm_mma_kernel<<<GG, 256, GSMEM_BYTES>>>(1, 0);
    lif_bn_kernel<<<(BNC/4 + 255)/256, 256>>>(bk, bn_k, 1, nullptr);

    gemm_mma_kernel<<<GG, 256, GSMEM_BYTES>>>(2, 0);
    lif_bn_kernel<<<(BNC/4 + 255)/256, 256>>>(nullptr, bn_v, 2, vout);

    kv_count_kernel<<<TT*BB*8, 256>>>();
    lif_kv_kernel<<<(BB*8*64 + 255)/256, 256>>>();

    gemm_mma_kernel<<<GG, 256, GSMEM_BYTES>>>(0, 0);
    lif_bn_kernel<<<(BNC/4 + 255)/256, 256>>>(bq, bn_q, 0, nullptr);

    gemm_mma_kernel<<<GG, 256, GSMEM_BYTES>>>(3, 1);
    out_kernel<<<(TBNC/4 + 255)/256, 256>>>(x, bp, bn_p, out);
}

// round 16
// speedup vs baseline: 3.5683x; 1.3781x over previous
#include <cuda_runtime.h>
#include <cuda_fp16.h>
#include <cstdint>

#define TT 4
#define BB 16
#define NTOK 1024
#define CC 512
#define BNC (BB*NTOK*CC)        /* 8388608  */
#define TBNC (TT*BNC)           /* 33554432 */

// ---------------- scratch ----------------
__device__ __half        g_xs_h[TBNC];
__device__ __half        g_k_h[TBNC];
__device__ __half        g_v_h[TBNC];
__device__ __half        g_att_h[TBNC];
__device__ float         g_Y[TBNC];
__device__ __half        g_wt[4][2][CC*CC];
__device__ int           g_kvcnt[TT*BB*8*64];
__device__ unsigned short g_kvspk[TT*BB*8*64];

#define H_ONE 0x3C00u   /* fp16 1.0 */

// ---------------- PTX helpers (sm_80-compatible only) ----------------
__device__ __forceinline__ uint32_t smem_u32(const void* p) {
    uint32_t a;
    asm("{ .reg .u64 t; cvta.to.shared.u64 t, %1; cvt.u32.u64 %0, t; }" : "=r"(a) : "l"(p));
    return a;
}
__device__ __forceinline__ void cp_async16(uint32_t dst, const void* src) {
    asm volatile("cp.async.cg.shared.global [%0], [%1], 16;" :: "r"(dst), "l"(src));
}
#define CP_COMMIT() asm volatile("cp.async.commit_group;" ::: "memory")
#define CP_WAIT(n)  asm volatile("cp.async.wait_group %0;" ::"n"(n) : "memory")

__device__ __forceinline__ void ldsm4(uint32_t& r0, uint32_t& r1, uint32_t& r2, uint32_t& r3, uint32_t addr) {
    asm volatile("ldmatrix.sync.aligned.m8n8.x4.shared.b16 {%0,%1,%2,%3}, [%4];"
                 : "=r"(r0), "=r"(r1), "=r"(r2), "=r"(r3) : "r"(addr));
}
__device__ __forceinline__ void mma_f16(float* c, const uint32_t* a, const uint32_t* b) {
    asm volatile("mma.sync.aligned.m16n8k16.row.col.f32.f16.f16.f32 "
                 "{%0,%1,%2,%3}, {%4,%5,%6,%7}, {%8,%9}, {%0,%1,%2,%3};"
                 : "+f"(c[0]), "+f"(c[1]), "+f"(c[2]), "+f"(c[3])
                 : "r"(a[0]), "r"(a[1]), "r"(a[2]), "r"(a[3]), "r"(b[0]), "r"(b[1]));
}

// ---------------- weight split + transpose: g_wt[w][s][n*512+k] (fp16 Dekker pair) ----------------
__global__ void wsplit_kernel(const float* __restrict__ W, int widx)
{
    __shared__ float t[32][33];
    int bx = blockIdx.x & 15, by = blockIdx.x >> 4;
    int x = threadIdx.x & 31, y = threadIdx.x >> 5;   // y: 0..7
    #pragma unroll
    for (int i = 0; i < 4; i++)
        t[y + 8*i][x] = W[(by*32 + y + 8*i)*512 + bx*32 + x];
    __syncthreads();
    #pragma unroll
    for (int i = 0; i < 4; i++) {
        float w = t[x][y + 8*i];
        int n = bx*32 + y + 8*i, k = by*32 + x;
        __half h0 = __float2half_rn(w);
        float r1 = w - __half2float(h0);
        __half h1 = __float2half_rn(r1);
        size_t o = (size_t)n*512 + k;
        g_wt[widx][0][o] = h0; g_wt[widx][1][o] = h1;
    }
}

// ---------------- HMMA GEMM: Y[M,512] = A(f16 {0,1})[M,512] @ (w0+w1)^T ----------------
// CTA 128x128, 8 warps (2M x 4N), warp tile 64x32. 16 stages: kc = s>>1 (K chunk of 64), split = s&1.
#define GSMEM_BYTES (65536 + 1024)

__device__ __forceinline__ void load_tile_128(uint32_t buf, const __half* src, int kc, int tid)
{
    // 128 rows x 64 fp16 (128B/row), SW128-xor swizzle; src row stride 512 fp16 (1024B)
    const char* s0 = (const char*)src + kc*128;
    #pragma unroll
    for (int it = 0; it < 4; it++) {
        int idx = it*256 + tid;              // 0..1023
        int r = idx >> 3, c16 = idx & 7;
        uint32_t off = (uint32_t)r*128 + c16*16;
        cp_async16(buf + (off ^ ((off >> 3) & 0x70)), s0 + (size_t)r*1024 + c16*16);
    }
}

__global__ __launch_bounds__(256, 2) void gemm_mma_kernel(int widx, int use_att)
{
    extern __shared__ char dsm[];
    uint32_t sb = (smem_u32(dsm) + 1023) & ~1023u;
    const uint32_t A_OFF = sb;               // 2 x 16KB
    const uint32_t B_OFF = sb + 32768;       // 2 x 16KB
    const int tid = threadIdx.x, lane = tid & 31, wid = tid >> 5;
    const int wm = wid >> 2, wn = wid & 3;   // warp grid 2(M) x 4(N)

    const int by = blockIdx.x >> 2, bx = blockIdx.x & 3;
    const __half* Asrc = (use_att ? g_att_h : g_xs_h) + (size_t)by*128*512;
    const __half* Wsrc0 = g_wt[widx][0] + (size_t)bx*128*512;
    const __half* Wsrc1 = g_wt[widx][1] + (size_t)bx*128*512;

    float acc[4][4][4];
    #pragma unroll
    for (int i = 0; i < 4; i++)
        #pragma unroll
        for (int j = 0; j < 4; j++)
            #pragma unroll
            for (int q = 0; q < 4; q++) acc[i][j][q] = 0.f;

    // prologue: stage 0 (A kc0 + B sp0), stage 1 (B sp1)
    load_tile_128(A_OFF, Asrc, 0, tid);
    load_tile_128(B_OFF, Wsrc0, 0, tid);
    CP_COMMIT();
    load_tile_128(B_OFF + 16384, Wsrc1, 0, tid);
    CP_COMMIT();

    for (int s = 0; s < 16; s++) {
        int kc = s >> 1;
        if (s < 15) CP_WAIT(1); else CP_WAIT(0);
        __syncthreads();

        // compute stage s
        {
            uint32_t abase = A_OFF + (kc & 1)*16384;
            uint32_t bbase = B_OFF + (s & 1)*16384;
            #pragma unroll
            for (int k16 = 0; k16 < 4; k16++) {
                uint32_t a[4][4];
                #pragma unroll
                for (int mb = 0; mb < 4; mb++) {
                    uint32_t row = wm*64 + mb*16 + (lane & 15);
                    uint32_t kb  = k16*32 + ((lane >> 4) << 4);
                    uint32_t off = row*128 + kb;
                    ldsm4(a[mb][0], a[mb][1], a[mb][2], a[mb][3],
                          abase + (off ^ ((off >> 3) & 0x70)));
                }
                uint32_t b[4][2];
                #pragma unroll
                for (int nb2 = 0; nb2 < 2; nb2++) {
                    uint32_t row = wn*32 + nb2*16 + (lane & 7) + ((lane >> 4) << 3);
                    uint32_t kb  = k16*32 + (((lane >> 3) & 1) << 4);
                    uint32_t off = row*128 + kb;
                    ldsm4(b[nb2*2][0], b[nb2*2][1], b[nb2*2+1][0], b[nb2*2+1][1],
                          bbase + (off ^ ((off >> 3) & 0x70)));
                }
                #pragma unroll
                for (int mb = 0; mb < 4; mb++)
                    #pragma unroll
                    for (int nb = 0; nb < 4; nb++)
                        mma_f16(acc[mb][nb], a[mb], b[nb]);
            }
        }
        __syncthreads();

        // issue stage s+2 loads (buffers just freed by the sync above)
        if (s + 2 < 16) {
            int s2 = s + 2;
            int kc2 = s2 >> 1, sp2 = s2 & 1;
            if (sp2 == 0) load_tile_128(A_OFF + (kc2 & 1)*16384, Asrc, kc2, tid);
            load_tile_128(B_OFF + (s2 & 1)*16384, sp2 ? Wsrc1 : Wsrc0, kc2, tid);
            CP_COMMIT();
        }
    }

    // epilogue: write f32 accumulators to g_Y
    const int gq = lane >> 2, qt = lane & 3;
    #pragma unroll
    for (int mb = 0; mb < 4; mb++) {
        #pragma unroll
        for (int nb = 0; nb < 4; nb++) {
            size_t row0 = (size_t)by*128 + wm*64 + mb*16 + gq;
            size_t col  = (size_t)bx*128 + wn*32 + nb*8 + qt*2;
            *(float2*)(g_Y + row0*512 + col)     = make_float2(acc[mb][nb][0], acc[mb][nb][1]);
            *(float2*)(g_Y + (row0+8)*512 + col) = make_float2(acc[mb][nb][2], acc[mb][nb][3]);
        }
    }
}

// ---------------- LIF over input x -> xs spikes (fp16) ----------------
__global__ void lif_x_kernel(const float* __restrict__ x)
{
    int i = blockIdx.x * blockDim.x + threadIdx.x;
    if (i >= BNC/4) return;
    const float4* x4 = (const float4*)x;
    uint2* xs2 = (uint2*)g_xs_h;
    float4 v = make_float4(0.f, 0.f, 0.f, 0.f);
    #pragma unroll
    for (int t = 0; t < TT; t++) {
        float4 xv = x4[t*(BNC/4) + i];
        v.x += (xv.x - v.x)*0.5f; v.y += (xv.y - v.y)*0.5f;
        v.z += (xv.z - v.z)*0.5f; v.w += (xv.w - v.w)*0.5f;
        unsigned s0 = (v.x >= 1.0f), s1 = (v.y >= 1.0f), s2 = (v.z >= 1.0f), s3 = (v.w >= 1.0f);
        if (s0) v.x = 0.f; if (s1) v.y = 0.f; if (s2) v.z = 0.f; if (s3) v.w = 0.f;
        uint2 o;
        o.x = (s0 ? H_ONE : 0u) | ((s1 ? H_ONE : 0u) << 16);
        o.y = (s2 ? H_ONE : 0u) | ((s3 ? H_ONE : 0u) << 16);
        xs2[t*(BNC/4) + i] = o;
    }
}

// ---------------- bn + LIF over Y -> fp16 spikes; sel: 0=q(+att mask), 1=k, 2=v(+vout) ----------------
__global__ void lif_bn_kernel(const float* __restrict__ bias,
                              const float* __restrict__ bnp,
                              int sel, float* __restrict__ vout)
{
    int i = blockIdx.x * blockDim.x + threadIdx.x;
    if (i >= BNC/4) return;
    const int c = (i & 127)*4;
    float4 ga = *(const float4*)(bnp + c);
    float4 be = *(const float4*)(bnp + 512 + c);
    float4 mu = *(const float4*)(bnp + 1024 + c);
    float4 va = *(const float4*)(bnp + 1536 + c);
    float4 rs;
    rs.x = rsqrtf(va.x + 1e-5f); rs.y = rsqrtf(va.y + 1e-5f);
    rs.z = rsqrtf(va.z + 1e-5f); rs.w = rsqrtf(va.w + 1e-5f);
    float4 bb = make_float4(0.f, 0.f, 0.f, 0.f);
    if (bias) bb = *(const float4*)(bias + c);

    uint2* dst = (sel == 0) ? (uint2*)g_att_h : (sel == 1) ? (uint2*)g_k_h : (uint2*)g_v_h;
    const float4* Y4 = (const float4*)g_Y;

    const int b = i >> 17;
    const int r = i & 131071;
    const int n = r >> 7;
    const int h = c >> 6;
    const int d = c & 63;

    float4 v = make_float4(0.f, 0.f, 0.f, 0.f);
    #pragma unroll
    for (int t = 0; t < TT; t++) {
        float4 y = Y4[t*(BNC/4) + i];
        float ux = ga.x*((y.x + bb.x) - mu.x)*rs.x + be.x;
        float uy = ga.y*((y.y + bb.y) - mu.y)*rs.y + be.y;
        float uz = ga.z*((y.z + bb.z) - mu.z)*rs.z + be.z;
        float uw = ga.w*((y.w + bb.w) - mu.w)*rs.w + be.w;
        v.x += (ux - v.x)*0.5f; v.y += (uy - v.y)*0.5f;
        v.z += (uz - v.z)*0.5f; v.w += (uw - v.w)*0.5f;
        unsigned s0 = (v.x >= 1.0f), s1 = (v.y >= 1.0f), s2 = (v.z >= 1.0f), s3 = (v.w >= 1.0f);
        if (s0) v.x = 0.f; if (s1) v.y = 0.f; if (s2) v.z = 0.f; if (s3) v.w = 0.f;
        uint2 o;
        o.x = (s0 ? H_ONE : 0u) | ((s1 ? H_ONE : 0u) << 16);
        o.y = (s2 ? H_ONE : 0u) | ((s3 ? H_ONE : 0u) << 16);
        if (sel == 0) {   // q: apply talking-heads kv mask -> att directly
            uint2 mm = *(const uint2*)(g_kvspk + ((t*BB + b)*8 + h)*64 + d);
            o.x &= mm.x; o.y &= mm.y;
        }
        dst[t*(BNC/4) + i] = o;
        if (sel == 2 && vout) {
            float4 fs = make_float4((float)s0, (float)s1, (float)s2, (float)s3);
            *(float4*)(vout + ((((size_t)(t*BB + b)*8 + h)*1024 + n)*64 + d)) = fs;
        }
    }
}

// ---------------- kv = sum_n k*v (integer-exact, fp16 inputs) ----------------
__global__ void kv_count_kernel()
{
    const int bid = blockIdx.x;          // (t*16+b)*8+h
    const int tid = threadIdx.x;         // 256
    const int d4 = tid & 15, g = tid >> 4;
    const int h = bid & 7;
    const int tb = bid >> 3;
    const size_t base = (size_t)tb*1024*512 + h*64 + d4*4;
    int a0=0, a1=0, a2=0, a3=0;
    for (int nn = 0; nn < 64; nn++) {
        size_t off = base + (size_t)(g*64 + nn)*512;
        uint2 kk = *(const uint2*)(g_k_h + off);
        uint2 vv = *(const uint2*)(g_v_h + off);
        unsigned m0 = kk.x & vv.x, m1 = kk.y & vv.y;
        a0 += (m0 & 0xFFFFu) ? 1 : 0; a1 += (m0 >> 16) ? 1 : 0;
        a2 += (m1 & 0xFFFFu) ? 1 : 0; a3 += (m1 >> 16) ? 1 : 0;
    }
    __shared__ int4 s[16][16];
    s[g][d4] = make_int4(a0, a1, a2, a3);
    __syncthreads();
    if (tid < 16) {
        int4 tot = make_int4(0, 0, 0, 0);
        #pragma unroll
        for (int gg = 0; gg < 16; gg++) {
            tot.x += s[gg][tid].x; tot.y += s[gg][tid].y;
            tot.z += s[gg][tid].z; tot.w += s[gg][tid].w;
        }
        ((int4*)g_kvcnt)[bid*16 + tid] = tot;
    }
}

__global__ void lif_kv_kernel()
{
    int i = blockIdx.x * blockDim.x + threadIdx.x;   // BB*8*64 = 8192
    if (i >= BB*8*64) return;
    float m = 0.f;
    #pragma unroll
    for (int t = 0; t < TT; t++) {
        float cnt = (float)g_kvcnt[t*8192 + i];
        m += (cnt - m)*0.5f;
        unsigned short sm = (m >= 0.5f) ? 0xFFFFu : 0u;
        g_kvspk[t*8192 + i] = sm;
        if (sm) m = 0.f;
    }
}

// ---------------- final bn + identity ----------------
__global__ void out_kernel(const float* __restrict__ x,
                           const float* __restrict__ bp,
                           const float* __restrict__ bnp,
                           float* __restrict__ out)
{
    int i = blockIdx.x * blockDim.x + threadIdx.x;   // TBNC/4
    if (i >= TBNC/4) return;
    const int c = (i & 127)*4;
    float4 ga = *(const float4*)(bnp + c);
    float4 be = *(const float4*)(bnp + 512 + c);
    float4 mu = *(const float4*)(bnp + 1024 + c);
    float4 va = *(const float4*)(bnp + 1536 + c);
    float4 b  = *(const float4*)(bp + c);
    float4 y  = ((const float4*)g_Y)[i];
    float4 xv = ((const float4*)x)[i];
    float4 o;
    o.x = ga.x*((y.x + b.x) - mu.x)*rsqrtf(va.x + 1e-5f) + be.x + xv.x;
    o.y = ga.y*((y.y + b.y) - mu.y)*rsqrtf(va.y + 1e-5f) + be.y + xv.y;
    o.z = ga.z*((y.z + b.z) - mu.z)*rsqrtf(va.z + 1e-5f) + be.z + xv.z;
    o.w = ga.w*((y.w + b.w) - mu.w)*rsqrtf(va.w + 1e-5f) + be.w + xv.w;
    ((float4*)out)[i] = o;
}

// ---------------- launch ----------------
extern "C" void kernel_launch(void* const* d_in, const int* in_sizes, int n_in,
                              void* d_out, int out_size)
{
    const float* x    = (const float*)d_in[0];
    const float* Wq   = (const float*)d_in[1];
    const float* bq   = (const float*)d_in[2];
    const float* Wk   = (const float*)d_in[3];
    const float* bk   = (const float*)d_in[4];
    const float* Wv   = (const float*)d_in[5];
    const float* Wp   = (const float*)d_in[6];
    const float* bp   = (const float*)d_in[7];
    const float* bn_q = (const float*)d_in[8];
    const float* bn_k = (const float*)d_in[9];
    const float* bn_v = (const float*)d_in[10];
    const float* bn_p = (const float*)d_in[11];
    float* out  = (float*)d_out;
    float* vout = (out_size >= 2*TBNC) ? (out + TBNC) : nullptr;

    cudaFuncSetAttribute(gemm_mma_kernel, cudaFuncAttributeMaxDynamicSharedMemorySize, GSMEM_BYTES);

    lif_x_kernel<<<(BNC/4 + 255)/256, 256>>>(x);
    wsplit_kernel<<<256, 256>>>(Wq, 0);
    wsplit_kernel<<<256, 256>>>(Wk, 1);
    wsplit_kernel<<<256, 256>>>(Wv, 2);
    wsplit_kernel<<<256, 256>>>(Wp, 3);

    const int GG = 512*4;   // (65536/128) x (512/128)

    // K, then V, then kv, then Q (att fused), then P
    gemm_mma_kernel<<<GG, 256, GSMEM_BYTES>>>(1, 0);
    lif_bn_kernel<<<(BNC/4 + 255)/256, 256>>>(bk, bn_k, 1, nullptr);

    gemm_mma_kernel<<<GG, 256, GSMEM_BYTES>>>(2, 0);
    lif_bn_kernel<<<(BNC/4 + 255)/256, 256>>>(nullptr, bn_v, 2, vout);

    kv_count_kernel<<<TT*BB*8, 256>>>();
    lif_kv_kernel<<<(BB*8*64 + 255)/256, 256>>>();

    gemm_mma_kernel<<<GG, 256, GSMEM_BYTES>>>(0, 0);
    lif_bn_kernel<<<(BNC/4 + 255)/256, 256>>>(bq, bn_q, 0, nullptr);

    gemm_mma_kernel<<<GG, 256, GSMEM_BYTES>>>(3, 1);
    out_kernel<<<(TBNC/4 + 255)/256, 256>>>(x, bp, bn_p, out);
}